// round 1
// baseline (speedup 1.0000x reference)
#include <cuda_runtime.h>
#include <cuda_bf16.h>

#define NB 4
#define NH 480
#define NW 640
#define NT 32
#define HW (NH*NW)
#define NPIX (NB*HW)

__global__ __launch_bounds__(256) void evsim_kernel(
    const float* __restrict__ log_images,
    const float* __restrict__ image_ts,
    const float* __restrict__ first_times,
    const float* __restrict__ thresholds,
    const float* __restrict__ log_states,
    const float* __restrict__ timestamps,
    const float* __restrict__ prev_image_ts,
    const float* __restrict__ refractory,
    const float* __restrict__ leak_rates,
    const float* __restrict__ shot_rates,
    const float* __restrict__ threshold_mus,
    const float* __restrict__ rng,
    float* __restrict__ out)
{
    int idx = blockIdx.x * blockDim.x + threadIdx.x;
    if (idx >= NPIX) return;
    int b = idx / HW;          // warp-uniform (HW = 307200 is a multiple of 256)
    int p = idx - b * HW;      // h*W + w

    // frames for this pixel: 32 contiguous floats = exactly one 128B line
    const float4* fbase =
        reinterpret_cast<const float4*>(log_images + ((size_t)p * NB + b) * NT);

    float th_off = thresholds[idx];
    float th_on  = thresholds[NPIX + idx];
    float ref    = __ldg(&refractory[b]);
    float leak   = __ldg(&leak_rates[b]);
    float shot   = __ldg(&shot_rates[b]);
    float mu_on  = __ldg(&threshold_mus[2 * b + 1]);
    bool  ft     = __ldg(&first_times[b]) > 0.0f;

    float4 cur = fbase[0];

    float state, ts_prev, last;
    float counts = 0.0f;

    if (ft) {
        state   = cur.x;                       // frames[0]
        ts_prev = __ldg(&image_ts[b * NT]);    // image_ts[b, 0]
        last    = __fsub_rn(ts_prev, ref);     // ts0 - refractory
    } else {
        state   = log_states[idx];
        ts_prev = __ldg(&prev_image_ts[b]);
        last    = timestamps[idx];
    }

    #pragma unroll
    for (int c = 0; c < 8; c++) {
        float4 nxt = (c < 7) ? fbase[c + 1] : cur;   // double-buffer frame chunk
        float fr[4] = {cur.x, cur.y, cur.z, cur.w};
        #pragma unroll
        for (int j = 0; j < 4; j++) {
            const int t = c * 4 + j;
            if (t == 0) continue;                    // t=0 only seeds state

            float ts_t = __ldg(&image_ts[b * NT + t]);
            float u    = __ldg(&rng[(size_t)(t * NB + b) * HW + p]); // coalesced

            float dt = __fsub_rn(ts_t, ts_prev);

            // state -= leak * dt * mu_on   (left-assoc, unfused, IEEE rn)
            state = __fsub_rn(state, __fmul_rn(__fmul_rn(leak, dt), mu_on));

            float diff = __fsub_rn(fr[j], state);
            bool  pos  = (diff >= 0.0f);
            float th   = pos ? th_on : th_off;

            // n = floor(|diff| / th) — exact IEEE division, never approx
            float n = floorf(__fdiv_rn(fabsf(diff), th));
            if (!(__fsub_rn(ts_t, last) >= ref)) n = 0.0f;   // refractory gate

            float poln = pos ? n : (0.0f - n);
            state  = __fadd_rn(state, __fmul_rn(poln, th));
            counts = __fadd_rn(counts, poln);                // integer-exact
            if (n > 0.0f) last = ts_t;

            // shot noise (uses the just-updated `last`, matching reference order)
            float pr = __fmul_rn(shot, dt);
            if ((u < pr) && (__fsub_rn(ts_t, last) >= ref)) {
                counts = __fadd_rn(counts,
                                   (u < __fmul_rn(0.5f, pr)) ? 1.0f : -1.0f);
                last = ts_t;
            }

            ts_prev = ts_t;
        }
        cur = nxt;
    }

    out[idx] = counts;
}

extern "C" void kernel_launch(void* const* d_in, const int* in_sizes, int n_in,
                              void* d_out, int out_size) {
    const float* log_images    = (const float*)d_in[0];
    /* d_in[1] = video_len (int64) — unused by the reference computation */
    const float* image_ts      = (const float*)d_in[2];
    const float* first_times   = (const float*)d_in[3];
    const float* thresholds    = (const float*)d_in[4];
    const float* log_states    = (const float*)d_in[5];
    const float* timestamps    = (const float*)d_in[6];
    const float* prev_image_ts = (const float*)d_in[7];
    const float* refractory    = (const float*)d_in[8];
    const float* leak_rates    = (const float*)d_in[9];
    const float* shot_rates    = (const float*)d_in[10];
    const float* threshold_mus = (const float*)d_in[11];
    const float* rng           = (const float*)d_in[12];
    float* out = (float*)d_out;

    const int threads = 256;
    const int blocks  = (NPIX + threads - 1) / threads;  // 4800
    evsim_kernel<<<blocks, threads>>>(log_images, image_ts, first_times,
                                      thresholds, log_states, timestamps,
                                      prev_image_ts, refractory, leak_rates,
                                      shot_rates, threshold_mus, rng, out);
}

// round 2
// speedup vs baseline: 1.2904x; 1.2904x over previous
#include <cuda_runtime.h>
#include <cuda_bf16.h>

#define NB 4
#define NH 480
#define NW 640
#define NT 32
#define HW (NH*NW)
#define NPIX (NB*HW)
#define PPB 512                    // pixels (p values) per block (256 thr x 2)
#define BLKS_PER_B (HW/PPB)        // 600

__global__ __launch_bounds__(256, 4) void evsim2_kernel(
    const float* __restrict__ log_images,
    const float* __restrict__ image_ts,
    const float* __restrict__ first_times,
    const float* __restrict__ thresholds,
    const float* __restrict__ log_states,
    const float* __restrict__ timestamps,
    const float* __restrict__ prev_image_ts,
    const float* __restrict__ refractory,
    const float* __restrict__ leak_rates,
    const float* __restrict__ shot_rates,
    const float* __restrict__ threshold_mus,
    const float* __restrict__ rng,
    float* __restrict__ out)
{
    __shared__ float ts_sh[NT];    // image_ts[b, t]
    __shared__ float lmdt_sh[NT];  // (leak*dt)*mu_on   (block-uniform, exact rn)
    __shared__ float pr_sh[NT];    // shot*dt
    __shared__ float prh_sh[NT];   // 0.5*(shot*dt)

    const int b  = blockIdx.x / BLKS_PER_B;                    // uniform per block
    const int p0 = (blockIdx.x % BLKS_PER_B) * PPB + threadIdx.x * 2;

    const float ref   = __ldg(&refractory[b]);
    const float leak  = __ldg(&leak_rates[b]);
    const float shot  = __ldg(&shot_rates[b]);
    const float mu_on = __ldg(&threshold_mus[2 * b + 1]);
    const bool  ft    = __ldg(&first_times[b]) > 0.0f;

    if (threadIdx.x < NT) {
        const int t = threadIdx.x;
        float tst = __ldg(&image_ts[b * NT + t]);
        ts_sh[t] = tst;
        float tsp;
        if (t == 0)      tsp = tst;                                         // unused
        else if (t == 1) tsp = ft ? __ldg(&image_ts[b * NT])
                                  : __ldg(&prev_image_ts[b]);               // ts0
        else             tsp = __ldg(&image_ts[b * NT + t - 1]);
        float dt = __fsub_rn(tst, tsp);
        lmdt_sh[t] = __fmul_rn(__fmul_rn(leak, dt), mu_on);
        float pr   = __fmul_rn(shot, dt);
        pr_sh[t]   = pr;
        prh_sh[t]  = __fmul_rn(0.5f, pr);
    }
    __syncthreads();

    const int idx = b * HW + p0;                 // even -> float2 aligned
    const float2 thoff = *reinterpret_cast<const float2*>(thresholds + idx);
    const float2 thon  = *reinterpret_cast<const float2*>(thresholds + NPIX + idx);

    // each pixel's 32 frames are one contiguous 128B line
    const float4* f0 = reinterpret_cast<const float4*>(
        log_images + ((size_t)p0 * NB + b) * NT);
    const float4* f1 = reinterpret_cast<const float4*>(
        log_images + ((size_t)(p0 + 1) * NB + b) * NT);

    float4 curA = f0[0];
    float4 curB = f1[0];

    float s0, s1, l0, l1;
    float c0 = 0.0f, c1 = 0.0f;
    if (ft) {
        s0 = curA.x; s1 = curB.x;
        l0 = l1 = __fsub_rn(ts_sh[0], ref);
    } else {
        s0 = log_states[idx];     s1 = log_states[idx + 1];
        l0 = timestamps[idx];     l1 = timestamps[idx + 1];
    }

    const float* ubase = rng + (size_t)b * HW + p0;

    #pragma unroll
    for (int c = 0; c < 8; c++) {
        // front-batch next frame chunk + this chunk's rng: 6 loads in flight
        float4 nA = (c < 7) ? f0[c + 1] : curA;
        float4 nB = (c < 7) ? f1[c + 1] : curB;
        float2 u[4];
        u[0] = make_float2(0.f, 0.f);
        #pragma unroll
        for (int j = 0; j < 4; j++) {
            const int t = c * 4 + j;
            if (t > 0)
                u[j] = *reinterpret_cast<const float2*>(
                           ubase + (size_t)t * (NB * HW));
        }
        float frA[4] = {curA.x, curA.y, curA.z, curA.w};
        float frB[4] = {curB.x, curB.y, curB.z, curB.w};

        #pragma unroll
        for (int j = 0; j < 4; j++) {
            const int t = c * 4 + j;
            if (t == 0) continue;                 // t=0 only seeds state

            const float ts_t = ts_sh[t];
            const float lmdt = lmdt_sh[t];
            const float pr   = pr_sh[t];
            const float prh  = prh_sh[t];

            // ---- pixel 0 ----
            {
                s0 = __fsub_rn(s0, lmdt);
                float d   = __fsub_rn(frA[j], s0);
                bool  pos = (d >= 0.0f);
                float th  = pos ? thon.x : thoff.x;
                float n   = floorf(__fdiv_rn(fabsf(d), th));
                if (!(__fsub_rn(ts_t, l0) >= ref)) n = 0.0f;
                float pn  = pos ? n : (0.0f - n);
                s0 = __fadd_rn(s0, __fmul_rn(pn, th));
                c0 = __fadd_rn(c0, pn);
                if (n > 0.0f) l0 = ts_t;
                float uu = u[j].x;
                if ((uu < pr) && (__fsub_rn(ts_t, l0) >= ref)) {
                    c0 = __fadd_rn(c0, (uu < prh) ? 1.0f : -1.0f);
                    l0 = ts_t;
                }
            }
            // ---- pixel 1 ----
            {
                s1 = __fsub_rn(s1, lmdt);
                float d   = __fsub_rn(frB[j], s1);
                bool  pos = (d >= 0.0f);
                float th  = pos ? thon.y : thoff.y;
                float n   = floorf(__fdiv_rn(fabsf(d), th));
                if (!(__fsub_rn(ts_t, l1) >= ref)) n = 0.0f;
                float pn  = pos ? n : (0.0f - n);
                s1 = __fadd_rn(s1, __fmul_rn(pn, th));
                c1 = __fadd_rn(c1, pn);
                if (n > 0.0f) l1 = ts_t;
                float uu = u[j].y;
                if ((uu < pr) && (__fsub_rn(ts_t, l1) >= ref)) {
                    c1 = __fadd_rn(c1, (uu < prh) ? 1.0f : -1.0f);
                    l1 = ts_t;
                }
            }
        }
        curA = nA;
        curB = nB;
    }

    *reinterpret_cast<float2*>(out + idx) = make_float2(c0, c1);
}

extern "C" void kernel_launch(void* const* d_in, const int* in_sizes, int n_in,
                              void* d_out, int out_size) {
    const float* log_images    = (const float*)d_in[0];
    /* d_in[1] = video_len (int64) — unused by the computation */
    const float* image_ts      = (const float*)d_in[2];
    const float* first_times   = (const float*)d_in[3];
    const float* thresholds    = (const float*)d_in[4];
    const float* log_states    = (const float*)d_in[5];
    const float* timestamps    = (const float*)d_in[6];
    const float* prev_image_ts = (const float*)d_in[7];
    const float* refractory    = (const float*)d_in[8];
    const float* leak_rates    = (const float*)d_in[9];
    const float* shot_rates    = (const float*)d_in[10];
    const float* threshold_mus = (const float*)d_in[11];
    const float* rng           = (const float*)d_in[12];
    float* out = (float*)d_out;

    const int blocks = NB * BLKS_PER_B;   // 2400
    evsim2_kernel<<<blocks, 256>>>(log_images, image_ts, first_times,
                                   thresholds, log_states, timestamps,
                                   prev_image_ts, refractory, leak_rates,
                                   shot_rates, threshold_mus, rng, out);
}